// round 7
// baseline (speedup 1.0000x reference)
#include <cuda_runtime.h>

// ---------------------------------------------------------------------------
// Deformable Conv2d (B=8, Cin=128, H=W=64, Cout=256, K=3, pad=1) + BN + SiLU
//   1) x NCHW -> NHWC transpose
//   2) weight transposes: dconv_w -> w_t[k][cout], offset_w -> ow_t[k][18]
//   3) offset conv (thread-per-pixel, 18 accumulators, weights in smem)
//   4) fused bilinear-gather + register-blocked GEMM:
//        block = 32 pixels x 256 couts, thread = 8 couts x 4 px,
//        patch loads are warp-broadcast LDS.128, weights via coalesced LDG
//   5) BN reduce (deterministic tree) + finalize (normalize + SiLU)
// ---------------------------------------------------------------------------

constexpr int Bn   = 8;
constexpr int CIN  = 128;
constexpr int COUT = 256;
constexpr int KK   = 9;
constexpr int HW   = 64 * 64;          // 4096
constexpr int KDIM = CIN * KK;         // 1152
constexpr int PROW = 36;               // padded patch row (16B-aligned rows)

__device__ float g_xt[Bn * HW * CIN];            // NHWC x (16.8 MB)
__device__ float g_wt[(KDIM + 2) * COUT];        // w_t[k][cout]
__device__ float g_owt[KDIM * 18];               // ow_t[k][co]
__device__ float g_off[Bn * 18 * HW];            // offset conv output (NCHW)
__device__ float g_y[Bn * COUT * HW];            // conv output (NCHW)
__device__ float g_mean[COUT];
__device__ float g_rstd[COUT];

// ---------------- 1) x NCHW -> NHWC ----------------
__global__ void k_transpose_x(const float* __restrict__ x) {
    __shared__ float tile[32][33];
    int b   = blockIdx.z;
    int hw0 = blockIdx.x * 32;
    int c0  = blockIdx.y * 32;
    int tx = threadIdx.x, ty = threadIdx.y;
    tile[ty][tx] = x[(b * CIN + c0 + ty) * HW + hw0 + tx];
    __syncthreads();
    g_xt[(b * HW + hw0 + ty) * CIN + c0 + tx] = tile[tx][ty];
}

// ---------------- 2) weight transposes ----------------
__global__ void k_prep_w(const float* __restrict__ dw, const float* __restrict__ ow) {
    int tid = blockIdx.x * 256 + threadIdx.x;
    if (tid < KDIM * COUT) {
        int cout = tid & (COUT - 1);
        int k    = tid >> 8;
        int tap  = k >> 7;
        int c    = k & 127;
        g_wt[k * COUT + cout] = dw[(cout * CIN + c) * KK + tap];
    } else if (tid < (KDIM + 2) * COUT) {
        g_wt[tid] = 0.0f;
    } else if (tid < (KDIM + 2) * COUT + KDIM * 18) {
        int j  = tid - (KDIM + 2) * COUT;
        int co = j % 18;
        int k  = j / 18;
        int tap = k >> 7;
        int c   = k & 127;
        g_owt[k * 18 + co] = ow[(co * CIN + c) * KK + tap];
    }
}

// ---------------- 3) offset conv ----------------
__global__ void k_offset_conv(const float* __restrict__ offset_b) {
    extern __shared__ float w_sm[];             // 1152*18 floats
    int tid = threadIdx.x;
    for (int i = tid; i < KDIM * 18; i += 256) w_sm[i] = g_owt[i];
    __syncthreads();

    int pid = blockIdx.x * 256 + tid;
    int b   = pid >> 12;
    int rem = pid & 4095;
    int ho  = rem >> 6;
    int wo  = rem & 63;

    float acc[18];
#pragma unroll
    for (int co = 0; co < 18; ++co) acc[co] = offset_b[co];

#pragma unroll
    for (int tap = 0; tap < 9; ++tap) {
        int y = ho - 1 + tap / 3;
        int x = wo - 1 + tap % 3;
        if ((unsigned)y < 64u && (unsigned)x < 64u) {
            const float4* xp = reinterpret_cast<const float4*>(
                g_xt + (((b * 64 + y) * 64 + x) << 7));
            const float* wbase = w_sm + tap * 128 * 18;
#pragma unroll 1
            for (int c4 = 0; c4 < 32; ++c4) {
                float4 v = xp[c4];
                float vv[4] = {v.x, v.y, v.z, v.w};
#pragma unroll
                for (int j = 0; j < 4; ++j) {
                    float xv = vv[j];
                    const float2* wr = reinterpret_cast<const float2*>(
                        wbase + (c4 * 4 + j) * 18);
#pragma unroll
                    for (int q = 0; q < 9; ++q) {
                        float2 wv = wr[q];
                        acc[2 * q]     = fmaf(xv, wv.x, acc[2 * q]);
                        acc[2 * q + 1] = fmaf(xv, wv.y, acc[2 * q + 1]);
                    }
                }
            }
        }
    }
#pragma unroll
    for (int co = 0; co < 18; ++co)
        g_off[(b * 18 + co) * HW + rem] = acc[co];
}

// ---------------- 4) fused gather + register-blocked GEMM ----------------
// block = (b, ho, wo0): 32 pixels x all 256 couts.
// Thread tile: 8 couts x 4 px.  cg = tid&31 (couts cg*8..+7), pg = tid>>5
// (px pg*4..+3).  Patch loads broadcast within a warp; weights via LDG
// (coalesced 1KB/warp/k, L1-resident across the 8 warps).
__global__ void __launch_bounds__(256, 1) k_main(const float* __restrict__ dconv_b) {
    extern __shared__ float sm[];
    float* sm_patch = sm;                                    // 1152*36
    float* sm_wy = sm + KDIM * PROW;                         // 288
    float* sm_wx = sm_wy + 288;                              // 288
    int*   sm_y0 = reinterpret_cast<int*>(sm_wx + 288);      // 288
    int*   sm_x0 = sm_y0 + 288;                              // 288

    int tid = threadIdx.x;
    int bi  = blockIdx.x;
    int b   = bi >> 7;
    int rem = bi & 127;
    int ho  = rem >> 1;
    int wo0 = (rem & 1) << 5;

    // Phase A: sampling coordinates (9 taps x 32 px)
    for (int i = tid; i < 288; i += 256) {
        int tap = i >> 5, p = i & 31;
        int wo = wo0 + p;
        float dy = g_off[(b * 18 + tap * 2)     * HW + ho * 64 + wo];
        float dx = g_off[(b * 18 + tap * 2 + 1) * HW + ho * 64 + wo];
        float sy = (float)(ho - 1 + tap / 3) + dy;
        float sx = (float)(wo - 1 + tap % 3) + dx;
        float fy = floorf(sy), fx = floorf(sx);
        sm_y0[i] = (int)fy;
        sm_x0[i] = (int)fx;
        sm_wy[i] = sy - fy;
        sm_wx[i] = sx - fx;
    }
    __syncthreads();

    // Phase B: bilinear gather into smem patches
    int warp = tid >> 5, lane = tid & 31;
    for (int t = warp; t < 1152; t += 8) {
        int pair = t >> 2;
        int c    = ((t & 3) << 5) + lane;
        int tap  = pair >> 5, p = pair & 31;
        int y0 = sm_y0[pair], x0 = sm_x0[pair];
        float wy = sm_wy[pair], wx = sm_wx[pair];
        bool yv0 = (unsigned)y0       < 64u;
        bool yv1 = (unsigned)(y0 + 1) < 64u;
        bool xv0 = (unsigned)x0       < 64u;
        bool xv1 = (unsigned)(x0 + 1) < 64u;
        int yc0 = max(0, min(63, y0));
        int yc1 = max(0, min(63, y0 + 1));
        int xc0 = max(0, min(63, x0));
        int xc1 = max(0, min(63, x0 + 1));
        const float* xb = g_xt + (b * HW) * CIN + c;
        float v00 = (yv0 && xv0) ? xb[(yc0 * 64 + xc0) * CIN] : 0.f;
        float v01 = (yv0 && xv1) ? xb[(yc0 * 64 + xc1) * CIN] : 0.f;
        float v10 = (yv1 && xv0) ? xb[(yc1 * 64 + xc0) * CIN] : 0.f;
        float v11 = (yv1 && xv1) ? xb[(yc1 * 64 + xc1) * CIN] : 0.f;
        float val = (1.f - wy) * ((1.f - wx) * v00 + wx * v01)
                  +        wy  * ((1.f - wx) * v10 + wx * v11);
        sm_patch[(tap * 128 + c) * PROW + p] = val;
    }
    __syncthreads();

    // Phase C: GEMM, 8 couts x 4 px per thread.
    int cg = tid & 31;           // cout group: couts cg*8 .. cg*8+7
    int pg = tid >> 5;           // pixel group: px pg*4 .. pg*4+3

    float acc[8][4];
#pragma unroll
    for (int i = 0; i < 8; ++i)
#pragma unroll
        for (int j = 0; j < 4; ++j) acc[i][j] = 0.f;

    const float* wp = g_wt + cg * 8;              // + k*COUT
    const float* pp = sm_patch + pg * 4;          // + k*PROW

#pragma unroll 4
    for (int k = 0; k < KDIM; ++k) {
        float4 p  = *reinterpret_cast<const float4*>(pp + k * PROW);
        float4 wa = *reinterpret_cast<const float4*>(wp + k * COUT);
        float4 wb = *reinterpret_cast<const float4*>(wp + k * COUT + 4);
        float w[8] = {wa.x, wa.y, wa.z, wa.w, wb.x, wb.y, wb.z, wb.w};
        float pv[4] = {p.x, p.y, p.z, p.w};
#pragma unroll
        for (int i = 0; i < 8; ++i)
#pragma unroll
            for (int j = 0; j < 4; ++j)
                acc[i][j] = fmaf(w[i], pv[j], acc[i][j]);
    }

    // Write out: 8 couts x 4 px (float4 per cout)
#pragma unroll
    for (int i = 0; i < 8; ++i) {
        int co = cg * 8 + i;
        float bias = dconv_b[co];
        float4 o;
        o.x = acc[i][0] + bias;
        o.y = acc[i][1] + bias;
        o.z = acc[i][2] + bias;
        o.w = acc[i][3] + bias;
        *reinterpret_cast<float4*>(
            g_y + (b * COUT + co) * HW + ho * 64 + wo0 + pg * 4) = o;
    }
}

// ---------------- 5a) BN statistics (deterministic) ----------------
__global__ void k_bn_reduce() {
    int c = blockIdx.x;
    int tid = threadIdx.x;
    float s = 0.f, s2 = 0.f;
    for (int b = 0; b < Bn; ++b) {
        const float4* p = reinterpret_cast<const float4*>(g_y + (b * COUT + c) * HW);
        for (int i = tid; i < HW / 4; i += 256) {
            float4 v = p[i];
            s  += v.x + v.y + v.z + v.w;
            s2 += v.x * v.x + v.y * v.y + v.z * v.z + v.w * v.w;
        }
    }
    __shared__ float rs[256], rs2[256];
    rs[tid] = s; rs2[tid] = s2;
    __syncthreads();
    for (int o = 128; o > 0; o >>= 1) {
        if (tid < o) { rs[tid] += rs[tid + o]; rs2[tid] += rs2[tid + o]; }
        __syncthreads();
    }
    if (tid == 0) {
        float inv = 1.0f / (Bn * HW);
        float m = rs[0] * inv;
        float var = rs2[0] * inv - m * m;
        g_mean[c] = m;
        g_rstd[c] = rsqrtf(var + 1e-5f);
    }
}

// ---------------- 5b) normalize + SiLU ----------------
__global__ void k_finalize(const float* __restrict__ gamma,
                           const float* __restrict__ beta,
                           float* __restrict__ out) {
    int idx = blockIdx.x * 256 + threadIdx.x;
    int c = (idx >> 10) & 255;
    float m = g_mean[c];
    float scale = g_rstd[c] * gamma[c];
    float shift = beta[c] - m * scale;
    float4 v = reinterpret_cast<const float4*>(g_y)[idx];
    float4 o;
    { float z = v.x * scale + shift; o.x = z / (1.f + __expf(-z)); }
    { float z = v.y * scale + shift; o.y = z / (1.f + __expf(-z)); }
    { float z = v.z * scale + shift; o.z = z / (1.f + __expf(-z)); }
    { float z = v.w * scale + shift; o.w = z / (1.f + __expf(-z)); }
    reinterpret_cast<float4*>(out)[idx] = o;
}

// ---------------------------------------------------------------------------
extern "C" void kernel_launch(void* const* d_in, const int* in_sizes, int n_in,
                              void* d_out, int out_size) {
    const float* x  = (const float*)d_in[0];
    const float* ow = (const float*)d_in[1];
    const float* ob = (const float*)d_in[2];
    const float* dw = (const float*)d_in[3];
    const float* db = (const float*)d_in[4];
    const float* ga = (const float*)d_in[5];
    const float* be = (const float*)d_in[6];
    float* out = (float*)d_out;

    cudaFuncSetAttribute(k_offset_conv,
                         cudaFuncAttributeMaxDynamicSharedMemorySize, KDIM * 18 * 4);
    cudaFuncSetAttribute(k_main,
                         cudaFuncAttributeMaxDynamicSharedMemorySize,
                         (KDIM * PROW + 288 * 4) * 4);

    k_transpose_x<<<dim3(HW / 32, CIN / 32, Bn), dim3(32, 32)>>>(x);
    k_prep_w<<<1235, 256>>>(dw, ow);
    k_offset_conv<<<128, 256, KDIM * 18 * 4>>>(ob);
    k_main<<<1024, 256, (KDIM * PROW + 288 * 4) * 4>>>(db);
    k_bn_reduce<<<COUT, 256>>>();
    k_finalize<<<8192, 256>>>(ga, be, out);
}

// round 8
// speedup vs baseline: 1.3153x; 1.3153x over previous
#include <cuda_runtime.h>

// ---------------------------------------------------------------------------
// Deformable Conv2d (B=8, Cin=128, H=W=64, Cout=256, K=3, pad=1) + BN + SiLU
//   1) x NCHW -> NHWC transpose
//   2) weight transposes: dconv_w -> w_t[k][cout], offset_w -> ow_t[k][18]
//   3) offset conv (thread-per-pixel, 18 accumulators, weights in smem)
//   4) fused gather + smem-tiled GEMM:
//        block = 128 couts x 64 px (one row), k chunked by tap (128),
//        both operands in smem; warp tile 64c x 16px; thread 8c x 4px
//   5) BN reduce (deterministic tree) + finalize (normalize + SiLU)
// ---------------------------------------------------------------------------

constexpr int Bn   = 8;
constexpr int CIN  = 128;
constexpr int COUT = 256;
constexpr int KK   = 9;
constexpr int HW   = 64 * 64;          // 4096
constexpr int KDIM = CIN * KK;         // 1152

constexpr int CT   = 128;              // couts per block
constexpr int KC   = 128;              // k-chunk (= one tap, all 128 channels)
constexpr int PSTR = 68;               // padded px stride (16B-aligned)

__device__ float g_xt[Bn * HW * CIN];            // NHWC x (16.8 MB)
__device__ float g_wt[(KDIM + 2) * COUT];        // w_t[k][cout]
__device__ float g_owt[KDIM * 18];               // ow_t[k][co]
__device__ float g_off[Bn * 18 * HW];            // offset conv output (NCHW)
__device__ float g_y[Bn * COUT * HW];            // conv output (NCHW)
__device__ float g_mean[COUT];
__device__ float g_rstd[COUT];

// ---------------- 1) x NCHW -> NHWC ----------------
__global__ void k_transpose_x(const float* __restrict__ x) {
    __shared__ float tile[32][33];
    int b   = blockIdx.z;
    int hw0 = blockIdx.x * 32;
    int c0  = blockIdx.y * 32;
    int tx = threadIdx.x, ty = threadIdx.y;
    tile[ty][tx] = x[(b * CIN + c0 + ty) * HW + hw0 + tx];
    __syncthreads();
    g_xt[(b * HW + hw0 + ty) * CIN + c0 + tx] = tile[tx][ty];
}

// ---------------- 2) weight transposes ----------------
__global__ void k_prep_w(const float* __restrict__ dw, const float* __restrict__ ow) {
    int tid = blockIdx.x * 256 + threadIdx.x;
    if (tid < KDIM * COUT) {
        int cout = tid & (COUT - 1);
        int k    = tid >> 8;
        int tap  = k >> 7;
        int c    = k & 127;
        g_wt[k * COUT + cout] = dw[(cout * CIN + c) * KK + tap];
    } else if (tid < (KDIM + 2) * COUT) {
        g_wt[tid] = 0.0f;
    } else if (tid < (KDIM + 2) * COUT + KDIM * 18) {
        int j  = tid - (KDIM + 2) * COUT;
        int co = j % 18;
        int k  = j / 18;
        int tap = k >> 7;
        int c   = k & 127;
        g_owt[k * 18 + co] = ow[(co * CIN + c) * KK + tap];
    }
}

// ---------------- 3) offset conv ----------------
__global__ void k_offset_conv(const float* __restrict__ offset_b) {
    extern __shared__ float w_sm[];             // 1152*18 floats
    int tid = threadIdx.x;
    for (int i = tid; i < KDIM * 18; i += 256) w_sm[i] = g_owt[i];
    __syncthreads();

    int pid = blockIdx.x * 256 + tid;
    int b   = pid >> 12;
    int rem = pid & 4095;
    int ho  = rem >> 6;
    int wo  = rem & 63;

    float acc[18];
#pragma unroll
    for (int co = 0; co < 18; ++co) acc[co] = offset_b[co];

#pragma unroll
    for (int tap = 0; tap < 9; ++tap) {
        int y = ho - 1 + tap / 3;
        int x = wo - 1 + tap % 3;
        if ((unsigned)y < 64u && (unsigned)x < 64u) {
            const float4* xp = reinterpret_cast<const float4*>(
                g_xt + (((b * 64 + y) * 64 + x) << 7));
            const float* wbase = w_sm + tap * 128 * 18;
#pragma unroll 1
            for (int c4 = 0; c4 < 32; ++c4) {
                float4 v = xp[c4];
                float vv[4] = {v.x, v.y, v.z, v.w};
#pragma unroll
                for (int j = 0; j < 4; ++j) {
                    float xv = vv[j];
                    const float2* wr = reinterpret_cast<const float2*>(
                        wbase + (c4 * 4 + j) * 18);
#pragma unroll
                    for (int q = 0; q < 9; ++q) {
                        float2 wv = wr[q];
                        acc[2 * q]     = fmaf(xv, wv.x, acc[2 * q]);
                        acc[2 * q + 1] = fmaf(xv, wv.y, acc[2 * q + 1]);
                    }
                }
            }
        }
    }
#pragma unroll
    for (int co = 0; co < 18; ++co)
        g_off[(b * 18 + co) * HW + rem] = acc[co];
}

// ---------------- 4) fused gather + smem-tiled GEMM ----------------
// blockIdx.x = (b*64 + ho)*2 + ch  -> 1024 blocks
//   ch: cout half (128 couts), px tile = full row (64 px)
// smem: w_sm[128][128] | p_sm[128][68] | coords (9 taps x 64 px)
// warp tile 64c x 16px, thread tile 8c x 4px (32 accumulators)
__global__ void __launch_bounds__(256, 2) k_main(const float* __restrict__ dconv_b) {
    extern __shared__ float sm[];
    float* w_sm  = sm;                               // 16384
    float* p_sm  = sm + KC * CT;                     // 8704
    float* sm_wy = p_sm + KC * PSTR;                 // 576
    float* sm_wx = sm_wy + 576;                      // 576
    int*   sm_y0 = reinterpret_cast<int*>(sm_wx + 576);
    int*   sm_x0 = sm_y0 + 576;

    int tid  = threadIdx.x;
    int warp = tid >> 5, lane = tid & 31;
    int bi   = blockIdx.x;
    int ch   = bi & 1;
    int ho   = (bi >> 1) & 63;
    int b    = bi >> 7;

    // Phase A: sampling coordinates for 9 taps x 64 px
    for (int i = tid; i < 576; i += 256) {
        int tap = i >> 6, px = i & 63;
        float dy = g_off[(b * 18 + tap * 2)     * HW + ho * 64 + px];
        float dx = g_off[(b * 18 + tap * 2 + 1) * HW + ho * 64 + px];
        float sy = (float)(ho - 1 + tap / 3) + dy;
        float sx = (float)(px - 1 + tap % 3) + dx;
        float fy = floorf(sy), fx = floorf(sx);
        sm_y0[i] = (int)fy;
        sm_x0[i] = (int)fx;
        sm_wy[i] = sy - fy;
        sm_wx[i] = sx - fx;
    }

    // GEMM thread mapping
    int wc  = (warp >> 2) * 64 + (lane >> 2) * 8;    // cout within block half
    int wpx = (warp & 3) * 16 + (lane & 3) * 4;      // pixel base

    float acc[8][4];
#pragma unroll
    for (int i = 0; i < 8; ++i)
#pragma unroll
        for (int j = 0; j < 4; ++j) acc[i][j] = 0.f;

    __syncthreads();   // coords ready

    for (int tap = 0; tap < 9; ++tap) {
        // Load weight chunk: w_sm[c][cout] = g_wt[tap*128+c][ch*128+cout]
        {
            const float4* src = reinterpret_cast<const float4*>(
                g_wt + (tap * KC) * COUT + ch * CT);
            float4* dst = reinterpret_cast<float4*>(w_sm);
            // row r (128 rows): 32 float4 per row in w_sm, 64 float4 stride in g_wt
#pragma unroll 4
            for (int i = tid; i < KC * (CT / 4); i += 256) {
                int r = i >> 5, col = i & 31;
                dst[i] = src[r * (COUT / 4) + col];
            }
        }

        // Gather chunk: p_sm[c][px] for this tap, 4-px quads per thread
        for (int t = warp; t < 64; t += 8) {
            int pq = t >> 2;                          // px quad 0..15
            int c  = (t & 3) * 32 + lane;             // channel 0..127
            const float* xb = g_xt + (b * HW) * CIN + c;
            float val[4];
#pragma unroll
            for (int j = 0; j < 4; ++j) {
                int px = pq * 4 + j;
                int ci = tap * 64 + px;
                int y0 = sm_y0[ci], x0 = sm_x0[ci];
                float wy = sm_wy[ci], wx = sm_wx[ci];
                bool yv0 = (unsigned)y0       < 64u;
                bool yv1 = (unsigned)(y0 + 1) < 64u;
                bool xv0 = (unsigned)x0       < 64u;
                bool xv1 = (unsigned)(x0 + 1) < 64u;
                int yc0 = max(0, min(63, y0));
                int yc1 = max(0, min(63, y0 + 1));
                int xc0 = max(0, min(63, x0));
                int xc1 = max(0, min(63, x0 + 1));
                float v00 = (yv0 && xv0) ? xb[(yc0 * 64 + xc0) * CIN] : 0.f;
                float v01 = (yv0 && xv1) ? xb[(yc0 * 64 + xc1) * CIN] : 0.f;
                float v10 = (yv1 && xv0) ? xb[(yc1 * 64 + xc0) * CIN] : 0.f;
                float v11 = (yv1 && xv1) ? xb[(yc1 * 64 + xc1) * CIN] : 0.f;
                val[j] = (1.f - wy) * ((1.f - wx) * v00 + wx * v01)
                       +        wy  * ((1.f - wx) * v10 + wx * v11);
            }
            float4 v4 = {val[0], val[1], val[2], val[3]};
            *reinterpret_cast<float4*>(p_sm + c * PSTR + pq * 4) = v4;
        }
        __syncthreads();   // chunk staged

        // GEMM over this chunk
#pragma unroll 4
        for (int kk = 0; kk < KC; ++kk) {
            float4 p  = *reinterpret_cast<const float4*>(p_sm + kk * PSTR + wpx);
            float4 wa = *reinterpret_cast<const float4*>(w_sm + kk * CT + wc);
            float4 wb = *reinterpret_cast<const float4*>(w_sm + kk * CT + wc + 4);
            float w[8] = {wa.x, wa.y, wa.z, wa.w, wb.x, wb.y, wb.z, wb.w};
            float pv[4] = {p.x, p.y, p.z, p.w};
#pragma unroll
            for (int i = 0; i < 8; ++i)
#pragma unroll
                for (int j = 0; j < 4; ++j)
                    acc[i][j] = fmaf(w[i], pv[j], acc[i][j]);
        }
        __syncthreads();   // before next chunk overwrites smem
    }

    // Epilogue: 8 couts x 4 px per thread
#pragma unroll
    for (int i = 0; i < 8; ++i) {
        int co = ch * CT + wc + i;
        float bias = dconv_b[co];
        float4 o;
        o.x = acc[i][0] + bias;
        o.y = acc[i][1] + bias;
        o.z = acc[i][2] + bias;
        o.w = acc[i][3] + bias;
        *reinterpret_cast<float4*>(
            g_y + (b * COUT + co) * HW + ho * 64 + wpx) = o;
    }
}

// ---------------- 5a) BN statistics (deterministic) ----------------
__global__ void k_bn_reduce() {
    int c = blockIdx.x;
    int tid = threadIdx.x;
    float s = 0.f, s2 = 0.f;
    for (int b = 0; b < Bn; ++b) {
        const float4* p = reinterpret_cast<const float4*>(g_y + (b * COUT + c) * HW);
        for (int i = tid; i < HW / 4; i += 256) {
            float4 v = p[i];
            s  += v.x + v.y + v.z + v.w;
            s2 += v.x * v.x + v.y * v.y + v.z * v.z + v.w * v.w;
        }
    }
    __shared__ float rs[256], rs2[256];
    rs[tid] = s; rs2[tid] = s2;
    __syncthreads();
    for (int o = 128; o > 0; o >>= 1) {
        if (tid < o) { rs[tid] += rs[tid + o]; rs2[tid] += rs2[tid + o]; }
        __syncthreads();
    }
    if (tid == 0) {
        float inv = 1.0f / (Bn * HW);
        float m = rs[0] * inv;
        float var = rs2[0] * inv - m * m;
        g_mean[c] = m;
        g_rstd[c] = rsqrtf(var + 1e-5f);
    }
}

// ---------------- 5b) normalize + SiLU ----------------
__global__ void k_finalize(const float* __restrict__ gamma,
                           const float* __restrict__ beta,
                           float* __restrict__ out) {
    int idx = blockIdx.x * 256 + threadIdx.x;
    int c = (idx >> 10) & 255;
    float m = g_mean[c];
    float scale = g_rstd[c] * gamma[c];
    float shift = beta[c] - m * scale;
    float4 v = reinterpret_cast<const float4*>(g_y)[idx];
    float4 o;
    { float z = v.x * scale + shift; o.x = z / (1.f + __expf(-z)); }
    { float z = v.y * scale + shift; o.y = z / (1.f + __expf(-z)); }
    { float z = v.z * scale + shift; o.z = z / (1.f + __expf(-z)); }
    { float z = v.w * scale + shift; o.w = z / (1.f + __expf(-z)); }
    reinterpret_cast<float4*>(out)[idx] = o;
}

// ---------------------------------------------------------------------------
extern "C" void kernel_launch(void* const* d_in, const int* in_sizes, int n_in,
                              void* d_out, int out_size) {
    const float* x  = (const float*)d_in[0];
    const float* ow = (const float*)d_in[1];
    const float* ob = (const float*)d_in[2];
    const float* dw = (const float*)d_in[3];
    const float* db = (const float*)d_in[4];
    const float* ga = (const float*)d_in[5];
    const float* be = (const float*)d_in[6];
    float* out = (float*)d_out;

    constexpr int SMEM_MAIN =
        (KC * CT + KC * PSTR + 576 * 4) * 4;         // 109,568 B

    cudaFuncSetAttribute(k_offset_conv,
                         cudaFuncAttributeMaxDynamicSharedMemorySize, KDIM * 18 * 4);
    cudaFuncSetAttribute(k_main,
                         cudaFuncAttributeMaxDynamicSharedMemorySize, SMEM_MAIN);

    k_transpose_x<<<dim3(HW / 32, CIN / 32, Bn), dim3(32, 32)>>>(x);
    k_prep_w<<<1235, 256>>>(dw, ow);
    k_offset_conv<<<128, 256, KDIM * 18 * 4>>>(ob);
    k_main<<<1024, 256, SMEM_MAIN>>>(db);
    k_bn_reduce<<<COUT, 256>>>();
    k_finalize<<<8192, 256>>>(ga, be, out);
}

// round 10
// speedup vs baseline: 2.3990x; 1.8239x over previous
#include <cuda_runtime.h>
#include <cstdint>

// ---------------------------------------------------------------------------
// Deformable Conv2d (B=8, Cin=128, H=W=64, Cout=256, K=3, pad=1) + BN + SiLU
//   1) x NCHW -> NHWC transpose
//   2) k_prep_w: dconv_w -> tf32-rounded A tiles [ch][tap][cout][cin],
//      offset_w -> ow_t[k][18]
//   3) offset conv (scalar, unchanged)
//   4) k_main: warp-level mma.sync tf32 GEMM (HMMA tensor pipe).
//      block = (b, ho, ch): M=128 couts, N=64 px, K chunked per tap (128).
//      w_sm[128][132] (A, row-major m x k), p_sm[128][72] (B, k x n).
//      8 warps, warp tile 32c x 32px, m16n8k8 fragments, fp32 accum.
//   5) BN reduce + finalize (unchanged)
// ---------------------------------------------------------------------------

constexpr int Bn   = 8;
constexpr int CIN  = 128;
constexpr int COUT = 256;
constexpr int HW   = 4096;
constexpr int KDIM = 1152;

constexpr int WSTR = 132;             // w_sm row stride (floats), conflict-free
constexpr int PSTR = 72;              // p_sm row stride (floats), conflict-free

// smem layout (float indices)
constexpr int OFF_W   = 0;                       // 128*132 = 16896
constexpr int OFF_P   = 16896;                   // 128*72  = 9216
constexpr int OFF_WY  = 26112;                   // 576
constexpr int OFF_WX  = 26688;                   // 576
constexpr int OFF_Y0  = 27264;                   // 576 (int)
constexpr int OFF_X0  = 27840;                   // 576 (int)
constexpr int SMEM_FLOATS = 28416;
constexpr int SMEM_BYTES  = SMEM_FLOATS * 4;     // 113,664 B -> 2 CTAs/SM

__device__ float g_xt[Bn * HW * CIN];            // NHWC x (16.8 MB)
__device__ float g_wa[2 * 9 * 128 * 128];        // tf32 A tiles (1.18 MB)
__device__ float g_owt[KDIM * 18];
__device__ float g_off[Bn * 18 * HW];
__device__ float g_y[Bn * COUT * HW];
__device__ float g_mean[COUT];
__device__ float g_rstd[COUT];

__device__ __forceinline__ float to_tf32(float v) {
    float r;
    asm("cvt.rna.tf32.f32 %0, %1;" : "=f"(r) : "f"(v));
    return r;
}

__device__ __forceinline__ void mma_16n8k8(float* d, const uint32_t* a,
                                           const uint32_t* b) {
    asm volatile(
        "mma.sync.aligned.m16n8k8.row.col.f32.tf32.tf32.f32 "
        "{%0,%1,%2,%3}, {%4,%5,%6,%7}, {%8,%9}, {%0,%1,%2,%3};\n"
        : "+f"(d[0]), "+f"(d[1]), "+f"(d[2]), "+f"(d[3])
        : "r"(a[0]), "r"(a[1]), "r"(a[2]), "r"(a[3]), "r"(b[0]), "r"(b[1]));
}

// ---------------- 1) x NCHW -> NHWC ----------------
__global__ void k_transpose_x(const float* __restrict__ x) {
    __shared__ float tile[32][33];
    int b   = blockIdx.z;
    int hw0 = blockIdx.x * 32;
    int c0  = blockIdx.y * 32;
    int tx = threadIdx.x, ty = threadIdx.y;
    tile[ty][tx] = x[(b * CIN + c0 + ty) * HW + hw0 + tx];
    __syncthreads();
    g_xt[(b * HW + hw0 + ty) * CIN + c0 + tx] = tile[tx][ty];
}

// ---------------- 2) weight prep ----------------
__global__ void k_prep_w(const float* __restrict__ dw, const float* __restrict__ ow) {
    int tid = blockIdx.x * 256 + threadIdx.x;
    if (tid < 2 * 9 * 16384) {
        int img = tid >> 14;                   // ch*9 + tap
        int idx = tid & 16383;
        int r = idx >> 7, c = idx & 127;       // cout-local, cin
        int ch = img / 9, tap = img - ch * 9;
        g_wa[tid] = to_tf32(dw[((ch * 128 + r) * CIN + c) * 9 + tap]);
    } else if (tid < 2 * 9 * 16384 + KDIM * 18) {
        int j  = tid - 2 * 9 * 16384;
        int co = j % 18;
        int k  = j / 18;
        int tap = k >> 7, c = k & 127;
        g_owt[k * 18 + co] = ow[(co * CIN + c) * 9 + tap];
    }
}

// ---------------- 3) offset conv ----------------
__global__ void k_offset_conv(const float* __restrict__ offset_b) {
    extern __shared__ float w_sm[];
    int tid = threadIdx.x;
    for (int i = tid; i < KDIM * 18; i += 256) w_sm[i] = g_owt[i];
    __syncthreads();

    int pid = blockIdx.x * 256 + tid;
    int b   = pid >> 12;
    int rem = pid & 4095;
    int ho  = rem >> 6;
    int wo  = rem & 63;

    float acc[18];
#pragma unroll
    for (int co = 0; co < 18; ++co) acc[co] = offset_b[co];

#pragma unroll
    for (int tap = 0; tap < 9; ++tap) {
        int y = ho - 1 + tap / 3;
        int x = wo - 1 + tap % 3;
        if ((unsigned)y < 64u && (unsigned)x < 64u) {
            const float4* xp = reinterpret_cast<const float4*>(
                g_xt + (((b * 64 + y) * 64 + x) << 7));
            const float* wbase = w_sm + tap * 128 * 18;
#pragma unroll 1
            for (int c4 = 0; c4 < 32; ++c4) {
                float4 v = xp[c4];
                float vv[4] = {v.x, v.y, v.z, v.w};
#pragma unroll
                for (int j = 0; j < 4; ++j) {
                    float xv = vv[j];
                    const float2* wr = reinterpret_cast<const float2*>(
                        wbase + (c4 * 4 + j) * 18);
#pragma unroll
                    for (int q = 0; q < 9; ++q) {
                        float2 wv = wr[q];
                        acc[2 * q]     = fmaf(xv, wv.x, acc[2 * q]);
                        acc[2 * q + 1] = fmaf(xv, wv.y, acc[2 * q + 1]);
                    }
                }
            }
        }
    }
#pragma unroll
    for (int co = 0; co < 18; ++co)
        g_off[(b * 18 + co) * HW + rem] = acc[co];
}

// ---------------- 4) mma.sync tf32 main ----------------
// blockIdx.x = (b*64 + ho)*2 + ch. 8 warps: warp tile 32 couts x 32 px.
__global__ void __launch_bounds__(256, 2) k_main(const float* __restrict__ dconv_b) {
    extern __shared__ float sm[];
    float* w_sm  = sm + OFF_W;
    float* p_sm  = sm + OFF_P;
    float* sm_wy = sm + OFF_WY;
    float* sm_wx = sm + OFF_WX;
    int*   sm_y0 = reinterpret_cast<int*>(sm + OFF_Y0);
    int*   sm_x0 = reinterpret_cast<int*>(sm + OFF_X0);

    int tid = threadIdx.x, wid = tid >> 5, lane = tid & 31;
    int bi = blockIdx.x;
    int ch = bi & 1;
    int ho = (bi >> 1) & 63;
    int b  = bi >> 7;

    // Phase A: sampling coords, 9 taps x 64 px
    for (int i = tid; i < 576; i += 256) {
        int tap = i >> 6, px = i & 63;
        float dy = g_off[(b * 18 + tap * 2)     * HW + ho * 64 + px];
        float dx = g_off[(b * 18 + tap * 2 + 1) * HW + ho * 64 + px];
        float sy = (float)(ho - 1 + tap / 3) + dy;
        float sx = (float)(px - 1 + tap % 3) + dx;
        float fy = floorf(sy), fx = floorf(sx);
        sm_y0[i] = (int)fy;
        sm_x0[i] = (int)fx;
        sm_wy[i] = sy - fy;
        sm_wx[i] = sx - fx;
    }
    __syncthreads();

    // MMA thread mapping
    int g = lane >> 2, t = lane & 3;
    int wm = (wid >> 1) * 32;                  // cout base (0/32/64/96)
    int wn = (wid & 1) * 32;                   // px base (0/32)

    float acc[2][4][4];
#pragma unroll
    for (int im = 0; im < 2; ++im)
#pragma unroll
        for (int in = 0; in < 4; ++in)
#pragma unroll
            for (int j = 0; j < 4; ++j) acc[im][in][j] = 0.f;

    const float* xb = g_xt + b * HW * CIN;
    const uint32_t* wsm = reinterpret_cast<const uint32_t*>(w_sm);
    const uint32_t* psm = reinterpret_cast<const uint32_t*>(p_sm);
    int a_off0 = (wm + g) * WSTR + t;
    int a_off1 = (wm + 16 + g) * WSTR + t;
    int b_off  = t * PSTR + wn + g;

    for (int tap = 0; tap < 9; ++tap) {
        // stage A: copy tf32 weight tile [128 cout][128 k] -> w_sm[.][WSTR]
        {
            const float4* src = reinterpret_cast<const float4*>(
                g_wa + (ch * 9 + tap) * 16384);
            float4* dst = reinterpret_cast<float4*>(w_sm);
#pragma unroll 4
            for (int i = tid; i < 4096; i += 256) {
                int r = i >> 5, col = i & 31;
                dst[r * (WSTR / 4) + col] = src[i];
            }
        }

        // gather B: p_sm[c][px] (tf32-rounded), thread = (px quad, channel)
        for (int tt = wid; tt < 64; tt += 8) {
            int pq = tt >> 2;                  // px quad 0..15
            int c  = (tt & 3) * 32 + lane;     // channel 0..127
            const float* xc = xb + c;
            float val[4];
#pragma unroll
            for (int j = 0; j < 4; ++j) {
                int px = pq * 4 + j;
                int ci = tap * 64 + px;
                int y0 = sm_y0[ci], x0 = sm_x0[ci];
                float wy = sm_wy[ci], wx = sm_wx[ci];
                bool yv0 = (unsigned)y0       < 64u;
                bool yv1 = (unsigned)(y0 + 1) < 64u;
                bool xv0 = (unsigned)x0       < 64u;
                bool xv1 = (unsigned)(x0 + 1) < 64u;
                int yc0 = max(0, min(63, y0));
                int yc1 = max(0, min(63, y0 + 1));
                int xc0 = max(0, min(63, x0));
                int xc1 = max(0, min(63, x0 + 1));
                float v00 = (yv0 && xv0) ? xc[(yc0 * 64 + xc0) * CIN] : 0.f;
                float v01 = (yv0 && xv1) ? xc[(yc0 * 64 + xc1) * CIN] : 0.f;
                float v10 = (yv1 && xv0) ? xc[(yc1 * 64 + xc0) * CIN] : 0.f;
                float v11 = (yv1 && xv1) ? xc[(yc1 * 64 + xc1) * CIN] : 0.f;
                val[j] = to_tf32((1.f - wy) * ((1.f - wx) * v00 + wx * v01)
                               +        wy  * ((1.f - wx) * v10 + wx * v11));
            }
            float4 v4 = {val[0], val[1], val[2], val[3]};
            *reinterpret_cast<float4*>(p_sm + c * PSTR + pq * 4) = v4;
        }
        __syncthreads();   // operands staged

        // MMA over this tap's K=128 (16 k-steps of 8)
#pragma unroll 2
        for (int s = 0; s < 16; ++s) {
            int k0 = s * 8;
            uint32_t A0[4], A1[4];
            A0[0] = wsm[a_off0 + k0];
            A0[1] = wsm[a_off0 + 8 * WSTR + k0];
            A0[2] = wsm[a_off0 + k0 + 4];
            A0[3] = wsm[a_off0 + 8 * WSTR + k0 + 4];
            A1[0] = wsm[a_off1 + k0];
            A1[1] = wsm[a_off1 + 8 * WSTR + k0];
            A1[2] = wsm[a_off1 + k0 + 4];
            A1[3] = wsm[a_off1 + 8 * WSTR + k0 + 4];
            uint32_t Bv[4][2];
#pragma unroll
            for (int in = 0; in < 4; ++in) {
                Bv[in][0] = psm[b_off + k0 * PSTR + in * 8];
                Bv[in][1] = psm[b_off + (k0 + 4) * PSTR + in * 8];
            }
#pragma unroll
            for (int in = 0; in < 4; ++in) {
                mma_16n8k8(acc[0][in], A0, Bv[in]);
                mma_16n8k8(acc[1][in], A1, Bv[in]);
            }
        }
        __syncthreads();   // before next tap overwrites smem
    }

    // Epilogue: c0=(g,2t) c1=(g,2t+1) c2=(g+8,2t) c3=(g+8,2t+1)
#pragma unroll
    for (int im = 0; im < 2; ++im) {
        int r0 = ch * 128 + wm + im * 16 + g;
        int r1 = r0 + 8;
        float b0 = dconv_b[r0];
        float b1 = dconv_b[r1];
        float* y0p = g_y + (b * COUT + r0) * HW + ho * 64;
        float* y1p = g_y + (b * COUT + r1) * HW + ho * 64;
#pragma unroll
        for (int in = 0; in < 4; ++in) {
            int col = wn + in * 8 + 2 * t;
            float2 o0 = {acc[im][in][0] + b0, acc[im][in][1] + b0};
            float2 o1 = {acc[im][in][2] + b1, acc[im][in][3] + b1};
            *reinterpret_cast<float2*>(y0p + col) = o0;
            *reinterpret_cast<float2*>(y1p + col) = o1;
        }
    }
}

// ---------------- 5a) BN statistics (deterministic) ----------------
__global__ void k_bn_reduce() {
    int c = blockIdx.x;
    int tid = threadIdx.x;
    float s = 0.f, s2 = 0.f;
    for (int b = 0; b < Bn; ++b) {
        const float4* p = reinterpret_cast<const float4*>(g_y + (b * COUT + c) * HW);
        for (int i = tid; i < HW / 4; i += 256) {
            float4 v = p[i];
            s  += v.x + v.y + v.z + v.w;
            s2 += v.x * v.x + v.y * v.y + v.z * v.z + v.w * v.w;
        }
    }
    __shared__ float rs[256], rs2[256];
    rs[tid] = s; rs2[tid] = s2;
    __syncthreads();
    for (int o = 128; o > 0; o >>= 1) {
        if (tid < o) { rs[tid] += rs[tid + o]; rs2[tid] += rs2[tid + o]; }
        __syncthreads();
    }
    if (tid == 0) {
        float inv = 1.0f / (Bn * HW);
        float m = rs[0] * inv;
        float var = rs2[0] * inv - m * m;
        g_mean[c] = m;
        g_rstd[c] = rsqrtf(var + 1e-5f);
    }
}

// ---------------- 5b) normalize + SiLU ----------------
__global__ void k_finalize(const float* __restrict__ gamma,
                           const float* __restrict__ beta,
                           float* __restrict__ out) {
    int idx = blockIdx.x * 256 + threadIdx.x;
    int c = (idx >> 10) & 255;
    float m = g_mean[c];
    float scale = g_rstd[c] * gamma[c];
    float shift = beta[c] - m * scale;
    float4 v = reinterpret_cast<const float4*>(g_y)[idx];
    float4 o;
    { float z = v.x * scale + shift; o.x = z / (1.f + __expf(-z)); }
    { float z = v.y * scale + shift; o.y = z / (1.f + __expf(-z)); }
    { float z = v.z * scale + shift; o.z = z / (1.f + __expf(-z)); }
    { float z = v.w * scale + shift; o.w = z / (1.f + __expf(-z)); }
    reinterpret_cast<float4*>(out)[idx] = o;
}

// ---------------------------------------------------------------------------
extern "C" void kernel_launch(void* const* d_in, const int* in_sizes, int n_in,
                              void* d_out, int out_size) {
    const float* x  = (const float*)d_in[0];
    const float* ow = (const float*)d_in[1];
    const float* ob = (const float*)d_in[2];
    const float* dw = (const float*)d_in[3];
    const float* db = (const float*)d_in[4];
    const float* ga = (const float*)d_in[5];
    const float* be = (const float*)d_in[6];
    float* out = (float*)d_out;

    cudaFuncSetAttribute(k_offset_conv,
                         cudaFuncAttributeMaxDynamicSharedMemorySize, KDIM * 18 * 4);
    cudaFuncSetAttribute(k_main,
                         cudaFuncAttributeMaxDynamicSharedMemorySize, SMEM_BYTES);

    k_transpose_x<<<dim3(HW / 32, CIN / 32, Bn), dim3(32, 32)>>>(x);
    k_prep_w<<<(2 * 9 * 16384 + KDIM * 18 + 255) / 256, 256>>>(dw, ow);
    k_offset_conv<<<128, 256, KDIM * 18 * 4>>>(ob);
    k_main<<<1024, 256, SMEM_BYTES>>>(db);
    k_bn_reduce<<<COUT, 256>>>();
    k_finalize<<<8192, 256>>>(ga, be, out);
}

// round 12
// speedup vs baseline: 2.7417x; 1.1428x over previous
#include <cuda_runtime.h>
#include <cstdint>

// ---------------------------------------------------------------------------
// Deformable Conv2d (B=8, Cin=128, H=W=64, Cout=256, K=3, pad=1) + BN + SiLU
//   4) k_main: warp-level mma.sync tf32 GEMM, block = (b, ho, ch):
//      M=128 couts, N=64 px, K per tap (128).
//      - A pre-packed per-fragment in gmem -> 2x LDS.128 per warp per k-step
//      - B layout [px][k] stride 136 (bank-perfect b-frag LDS.32)
//      - gather: precomputed corner offsets + validity-folded weights
//        (double-buffered per tap), lane = channel quad -> LDG.128
// ---------------------------------------------------------------------------

constexpr int Bn   = 8;
constexpr int CIN  = 128;
constexpr int COUT = 256;
constexpr int HW   = 4096;
constexpr int KDIM = 1152;

constexpr int BSTR = 136;                       // p_sm row stride (floats)

// smem layout (float indices)
constexpr int OFF_W  = 0;                       // 16384 (packed A tile)
constexpr int OFF_P  = 16384;                   // 64*136 = 8704
constexpr int OFF_CI = 25088;                   // int4[2][64]  = 512 words
constexpr int OFF_CF = 25600;                   // float4[2][64] = 512 words
constexpr int SMEM_FLOATS = 26112;
constexpr int SMEM_BYTES  = SMEM_FLOATS * 4;    // 104,448 B -> 2 CTAs/SM

__device__ float g_xt[Bn * HW * CIN];           // NHWC x (16.8 MB)
__device__ float g_wa[2 * 9 * 128 * 128];       // fragment-packed tf32 A tiles
__device__ float g_owt[KDIM * 18];
__device__ float g_off[Bn * 18 * HW];
__device__ float g_y[Bn * COUT * HW];
__device__ float g_mean[COUT];
__device__ float g_rstd[COUT];

__device__ __forceinline__ float to_tf32(float v) {
    float r;
    asm("cvt.rna.tf32.f32 %0, %1;" : "=f"(r) : "f"(v));
    return r;
}

__device__ __forceinline__ void mma_16n8k8(float* d, const uint32_t* a,
                                           const uint32_t* b) {
    asm volatile(
        "mma.sync.aligned.m16n8k8.row.col.f32.tf32.tf32.f32 "
        "{%0,%1,%2,%3}, {%4,%5,%6,%7}, {%8,%9}, {%0,%1,%2,%3};\n"
        : "+f"(d[0]), "+f"(d[1]), "+f"(d[2]), "+f"(d[3])
        : "r"(a[0]), "r"(a[1]), "r"(a[2]), "r"(a[3]), "r"(b[0]), "r"(b[1]));
}

// ---------------- 1) x NCHW -> NHWC ----------------
__global__ void k_transpose_x(const float* __restrict__ x) {
    __shared__ float tile[32][33];
    int b   = blockIdx.z;
    int hw0 = blockIdx.x * 32;
    int c0  = blockIdx.y * 32;
    int tx = threadIdx.x, ty = threadIdx.y;
    tile[ty][tx] = x[(b * CIN + c0 + ty) * HW + hw0 + tx];
    __syncthreads();
    g_xt[(b * HW + hw0 + ty) * CIN + c0 + tx] = tile[tx][ty];
}

// ---------------- 2) weight prep ----------------
// Packed A image per (ch,tap): idx = ((s*8 + mt)*32 + lane)*4 + q
//   lane=(g,t): q0=(mt*16+g, 8s+t) q1=(mt*16+8+g, 8s+t)
//               q2=(mt*16+g, 8s+t+4) q3=(mt*16+8+g, 8s+t+4)
__global__ void k_prep_w(const float* __restrict__ dw, const float* __restrict__ ow) {
    int tid = blockIdx.x * 256 + threadIdx.x;
    if (tid < 2 * 9 * 16384) {
        int img  = tid >> 14;                  // ch*9 + tap
        int idx  = tid & 16383;
        int q    = idx & 3;
        int lane = (idx >> 2) & 31;
        int mt   = (idx >> 7) & 7;
        int s    = idx >> 10;
        int g = lane >> 2, t = lane & 3;
        int ch = img / 9, tap = img - ch * 9;
        int r = mt * 16 + (q & 1) * 8 + g;
        int k = s * 8 + t + (q >> 1) * 4;
        g_wa[tid] = to_tf32(dw[((ch * 128 + r) * CIN + k) * 9 + tap]);
    } else if (tid < 2 * 9 * 16384 + KDIM * 18) {
        int j  = tid - 2 * 9 * 16384;
        int co = j % 18;
        int k  = j / 18;
        int tap = k >> 7, c = k & 127;
        g_owt[k * 18 + co] = ow[(co * CIN + c) * 9 + tap];
    }
}

// ---------------- 3) offset conv ----------------
__global__ void k_offset_conv(const float* __restrict__ offset_b) {
    extern __shared__ float w_sm[];
    int tid = threadIdx.x;
    for (int i = tid; i < KDIM * 18; i += 256) w_sm[i] = g_owt[i];
    __syncthreads();

    int pid = blockIdx.x * 256 + tid;
    int b   = pid >> 12;
    int rem = pid & 4095;
    int ho  = rem >> 6;
    int wo  = rem & 63;

    float acc[18];
#pragma unroll
    for (int co = 0; co < 18; ++co) acc[co] = offset_b[co];

#pragma unroll
    for (int tap = 0; tap < 9; ++tap) {
        int y = ho - 1 + tap / 3;
        int x = wo - 1 + tap % 3;
        if ((unsigned)y < 64u && (unsigned)x < 64u) {
            const float4* xp = reinterpret_cast<const float4*>(
                g_xt + (((b * 64 + y) * 64 + x) << 7));
            const float* wbase = w_sm + tap * 128 * 18;
#pragma unroll 1
            for (int c4 = 0; c4 < 32; ++c4) {
                float4 v = xp[c4];
                float vv[4] = {v.x, v.y, v.z, v.w};
#pragma unroll
                for (int j = 0; j < 4; ++j) {
                    float xv = vv[j];
                    const float2* wr = reinterpret_cast<const float2*>(
                        wbase + (c4 * 4 + j) * 18);
#pragma unroll
                    for (int q = 0; q < 9; ++q) {
                        float2 wv = wr[q];
                        acc[2 * q]     = fmaf(xv, wv.x, acc[2 * q]);
                        acc[2 * q + 1] = fmaf(xv, wv.y, acc[2 * q + 1]);
                    }
                }
            }
        }
    }
#pragma unroll
    for (int co = 0; co < 18; ++co)
        g_off[(b * 18 + co) * HW + rem] = acc[co];
}

// ---------------- coord helper ----------------
__device__ __forceinline__ void compute_coords(int tap, int ho, int b,
                                               int4* ci, float4* cf, int px) {
    float dy = g_off[(b * 18 + tap * 2)     * HW + ho * 64 + px];
    float dx = g_off[(b * 18 + tap * 2 + 1) * HW + ho * 64 + px];
    float sy = (float)(ho - 1 + tap / 3) + dy;
    float sx = (float)(px - 1 + tap % 3) + dx;
    float fy = floorf(sy), fx = floorf(sx);
    int y0 = (int)fy, x0 = (int)fx;
    float wy = sy - fy, wx = sx - fx;
    float yv0 = ((unsigned)y0       < 64u) ? 1.f : 0.f;
    float yv1 = ((unsigned)(y0 + 1) < 64u) ? 1.f : 0.f;
    float xv0 = ((unsigned)x0       < 64u) ? 1.f : 0.f;
    float xv1 = ((unsigned)(x0 + 1) < 64u) ? 1.f : 0.f;
    int yc0 = max(0, min(63, y0));
    int yc1 = max(0, min(63, y0 + 1));
    int xc0 = max(0, min(63, x0));
    int xc1 = max(0, min(63, x0 + 1));
    int4 o;
    o.x = (yc0 * 64 + xc0) * 32;    // offsets in float4 units (CIN/4 = 32)
    o.y = (yc0 * 64 + xc1) * 32;
    o.z = (yc1 * 64 + xc0) * 32;
    o.w = (yc1 * 64 + xc1) * 32;
    float4 w;
    w.x = (1.f - wy) * (1.f - wx) * yv0 * xv0;
    w.y = (1.f - wy) * wx         * yv0 * xv1;
    w.z = wy         * (1.f - wx) * yv1 * xv0;
    w.w = wy         * wx         * yv1 * xv1;
    ci[px] = o;
    cf[px] = w;
}

// ---------------- 4) mma.sync tf32 main ----------------
// blockIdx.x = (b*64 + ho)*2 + ch. 8 warps: warp tile 32 couts x 32 px.
__global__ void __launch_bounds__(256, 2) k_main(const float* __restrict__ dconv_b) {
    extern __shared__ float sm[];
    float* w_sm = sm + OFF_W;
    float* p_sm = sm + OFF_P;
    int4*   ci  = reinterpret_cast<int4*>(sm + OFF_CI);     // [2][64]
    float4* cf  = reinterpret_cast<float4*>(sm + OFF_CF);   // [2][64]

    int tid = threadIdx.x, wid = tid >> 5, lane = tid & 31;
    int bi = blockIdx.x;
    int ch = bi & 1;
    int ho = (bi >> 1) & 63;
    int b  = bi >> 7;

    int g = lane >> 2, t = lane & 3;
    int wm = (wid >> 1) * 32;                  // cout base (0/32/64/96)
    int wn = (wid & 1) * 32;                   // px base (0/32)
    int mt0 = wm >> 4;                         // 16-row fragment tile index

    float acc[2][4][4];
#pragma unroll
    for (int im = 0; im < 2; ++im)
#pragma unroll
        for (int in = 0; in < 4; ++in)
#pragma unroll
            for (int j = 0; j < 4; ++j) acc[im][in][j] = 0.f;

    const float4* xb4 = reinterpret_cast<const float4*>(g_xt + b * HW * CIN);
    const float4* wA  = reinterpret_cast<const float4*>(w_sm) + mt0 * 32 + lane;
    const uint32_t* pB = reinterpret_cast<const uint32_t*>(p_sm) + (wn + g) * BSTR + t;

    // coords for tap 0
    if (tid < 64) compute_coords(0, ho, b, ci, cf, tid);
    __syncthreads();

    for (int tap = 0; tap < 9; ++tap) {
        int buf = tap & 1;

        // ---- stage A: straight copy of packed fragment image ----
        {
            const float4* src = reinterpret_cast<const float4*>(
                g_wa + (ch * 9 + tap) * 16384);
            float4* dst = reinterpret_cast<float4*>(w_sm);
#pragma unroll 8
            for (int i = tid; i < 4096; i += 256) dst[i] = src[i];
        }

        // ---- gather B: warp = px, lane = channel quad, LDG.128 ----
        const int4*   cib = ci + buf * 64;
        const float4* cfb = cf + buf * 64;
#pragma unroll 1
        for (int px = wid; px < 64; px += 8) {
            int4   o = cib[px];
            float4 w = cfb[px];
            float4 v00 = xb4[o.x + lane];
            float4 v01 = xb4[o.y + lane];
            float4 v10 = xb4[o.z + lane];
            float4 v11 = xb4[o.w + lane];
            float4 val;
            val.x = to_tf32(fmaf(w.w, v11.x, fmaf(w.z, v10.x,
                            fmaf(w.y, v01.x, w.x * v00.x))));
            val.y = to_tf32(fmaf(w.w, v11.y, fmaf(w.z, v10.y,
                            fmaf(w.y, v01.y, w.x * v00.y))));
            val.z = to_tf32(fmaf(w.w, v11.z, fmaf(w.z, v10.z,
                            fmaf(w.y, v01.z, w.x * v00.z))));
            val.w = to_tf32(fmaf(w.w, v11.w, fmaf(w.z, v10.w,
                            fmaf(w.y, v01.w, w.x * v00.w))));
            *reinterpret_cast<float4*>(p_sm + px * BSTR + lane * 4) = val;
        }

        // ---- coords for next tap (overlapped) ----
        if (tap < 8 && tid < 64)
            compute_coords(tap + 1, ho, b, ci + ((tap + 1) & 1) * 64,
                           cf + ((tap + 1) & 1) * 64, tid);
        __syncthreads();   // operands + next coords staged

        // ---- MMA over this tap's K=128 (16 k-steps of 8) ----
#pragma unroll 2
        for (int s = 0; s < 16; ++s) {
            float4 fa0 = wA[s * 256];          // mt0
            float4 fa1 = wA[s * 256 + 32];     // mt0+1
            uint32_t A0[4] = {__float_as_uint(fa0.x), __float_as_uint(fa0.y),
                              __float_as_uint(fa0.z), __float_as_uint(fa0.w)};
            uint32_t A1[4] = {__float_as_uint(fa1.x), __float_as_uint(fa1.y),
                              __float_as_uint(fa1.z), __float_as_uint(fa1.w)};
            int k0 = s * 8;
            uint32_t Bv[4][2];
#pragma unroll
            for (int in = 0; in < 4; ++in) {
                Bv[in][0] = pB[in * 8 * BSTR + k0];
                Bv[in][1] = pB[in * 8 * BSTR + k0 + 4];
            }
#pragma unroll
            for (int in = 0; in < 4; ++in) {
                mma_16n8k8(acc[0][in], A0, Bv[in]);
                mma_16n8k8(acc[1][in], A1, Bv[in]);
            }
        }
        __syncthreads();   // before next tap overwrites smem
    }

    // Epilogue: c0=(g,2t) c1=(g,2t+1) c2=(g+8,2t) c3=(g+8,2t+1)
#pragma unroll
    for (int im = 0; im < 2; ++im) {
        int r0 = ch * 128 + wm + im * 16 + g;
        int r1 = r0 + 8;
        float b0 = dconv_b[r0];
        float b1 = dconv_b[r1];
        float* y0p = g_y + (b * COUT + r0) * HW + ho * 64;
        float* y1p = g_y + (b * COUT + r1) * HW + ho * 64;
#pragma unroll
        for (int in = 0; in < 4; ++in) {
            int col = wn + in * 8 + 2 * t;
            float2 o0 = {acc[im][in][0] + b0, acc[im][in][1] + b0};
            float2 o1 = {acc[im][in][2] + b1, acc[im][in][3] + b1};
            *reinterpret_cast<float2*>(y0p + col) = o0;
            *reinterpret_cast<float2*>(y1p + col) = o1;
        }
    }
}

// ---------------- 5a) BN statistics (deterministic) ----------------
__global__ void k_bn_reduce() {
    int c = blockIdx.x;
    int tid = threadIdx.x;
    float s = 0.f, s2 = 0.f;
    for (int b = 0; b < Bn; ++b) {
        const float4* p = reinterpret_cast<const float4*>(g_y + (b * COUT + c) * HW);
        for (int i = tid; i < HW / 4; i += 256) {
            float4 v = p[i];
            s  += v.x + v.y + v.z + v.w;
            s2 += v.x * v.x + v.y * v.y + v.z * v.z + v.w * v.w;
        }
    }
    __shared__ float rs[256], rs2[256];
    rs[tid] = s; rs2[tid] = s2;
    __syncthreads();
    for (int o = 128; o > 0; o >>= 1) {
        if (tid < o) { rs[tid] += rs[tid + o]; rs2[tid] += rs2[tid + o]; }
        __syncthreads();
    }
    if (tid == 0) {
        float inv = 1.0f / (Bn * HW);
        float m = rs[0] * inv;
        float var = rs2[0] * inv - m * m;
        g_mean[c] = m;
        g_rstd[c] = rsqrtf(var + 1e-5f);
    }
}

// ---------------- 5b) normalize + SiLU ----------------
__global__ void k_finalize(const float* __restrict__ gamma,
                           const float* __restrict__ beta,
                           float* __restrict__ out) {
    int idx = blockIdx.x * 256 + threadIdx.x;
    int c = (idx >> 10) & 255;
    float m = g_mean[c];
    float scale = g_rstd[c] * gamma[c];
    float shift = beta[c] - m * scale;
    float4 v = reinterpret_cast<const float4*>(g_y)[idx];
    float4 o;
    { float z = v.x * scale + shift; o.x = z / (1.f + __expf(-z)); }
    { float z = v.y * scale + shift; o.y = z / (1.f + __expf(-z)); }
    { float z = v.z * scale + shift; o.z = z / (1.f + __expf(-z)); }
    { float z = v.w * scale + shift; o.w = z / (1.f + __expf(-z)); }
    reinterpret_cast<float4*>(out)[idx] = o;
}

// ---------------------------------------------------------------------------
extern "C" void kernel_launch(void* const* d_in, const int* in_sizes, int n_in,
                              void* d_out, int out_size) {
    const float* x  = (const float*)d_in[0];
    const float* ow = (const float*)d_in[1];
    const float* ob = (const float*)d_in[2];
    const float* dw = (const float*)d_in[3];
    const float* db = (const float*)d_in[4];
    const float* ga = (const float*)d_in[5];
    const float* be = (const float*)d_in[6];
    float* out = (float*)d_out;

    cudaFuncSetAttribute(k_offset_conv,
                         cudaFuncAttributeMaxDynamicSharedMemorySize, KDIM * 18 * 4);
    cudaFuncSetAttribute(k_main,
                         cudaFuncAttributeMaxDynamicSharedMemorySize, SMEM_BYTES);

    k_transpose_x<<<dim3(HW / 32, CIN / 32, Bn), dim3(32, 32)>>>(x);
    k_prep_w<<<(2 * 9 * 16384 + KDIM * 18 + 255) / 256, 256>>>(dw, ow);
    k_offset_conv<<<128, 256, KDIM * 18 * 4>>>(ob);
    k_main<<<1024, 256, SMEM_BYTES>>>(db);
    k_bn_reduce<<<COUT, 256>>>();
    k_finalize<<<8192, 256>>>(ga, be, out);
}

// round 17
// speedup vs baseline: 2.9523x; 1.0768x over previous
#include <cuda_runtime.h>
#include <cstdint>

// ---------------------------------------------------------------------------
// Deformable Conv2d (B=8, Cin=128, H=W=64, Cout=256, K=3, pad=1) + BN + SiLU
//   1) x NCHW -> NHWC transpose
//   2) k_prep_w: dconv_w + offset_w -> fragment-packed tf32 images
//   3) k_offset_mma: offset conv via mma.sync tf32 (M=32 padded from 18,
//      N=128 px/block, warp-independent, B = coalesced row copies)
//   4) k_main: mma.sync tf32, block = (b, ho-pair, ch): M=128 c x N=128 px,
//      K per tap (128). A fragments DIRECT from gmem (no smem roundtrip);
//      B gather double-buffered coords, [px][k] stride 132 (conflict-free).
//   5) BN reduce + finalize
// ---------------------------------------------------------------------------

constexpr int Bn   = 8;
constexpr int CIN  = 128;
constexpr int COUT = 256;
constexpr int HW   = 4096;

constexpr int BSTR = 132;                       // B row stride (floats)

// k_main smem layout (float indices)
constexpr int OFF_P  = 0;                       // 128*132 = 16896
constexpr int OFF_CI = 16896;                   // int4[2][128]  = 1024 words
constexpr int OFF_CF = 17920;                   // float4[2][128] = 1024 words
constexpr int SMEM_FLOATS = 18944;
constexpr int SMEM_BYTES  = SMEM_FLOATS * 4;    // 75,776 B -> 2 CTAs/SM

constexpr int OSM_BYTES = 128 * BSTR * 4;       // offset kernel smem 67,584 B

__device__ float g_xt[Bn * HW * CIN];           // NHWC x (16.8 MB)
__device__ float g_wa[2 * 9 * 128 * 128];       // fragment-packed tf32 A (main)
__device__ float g_owa[9 * 16 * 2 * 128];       // fragment-packed tf32 A (offset)
__device__ float g_off[Bn * 18 * HW];
__device__ float g_y[Bn * COUT * HW];
__device__ float g_mean[COUT];
__device__ float g_rstd[COUT];

__device__ __forceinline__ float to_tf32(float v) {
    float r;
    asm("cvt.rna.tf32.f32 %0, %1;" : "=f"(r) : "f"(v));
    return r;
}

__device__ __forceinline__ void mma_16n8k8(float* d, const uint32_t* a,
                                           const uint32_t* b) {
    asm volatile(
        "mma.sync.aligned.m16n8k8.row.col.f32.tf32.tf32.f32 "
        "{%0,%1,%2,%3}, {%4,%5,%6,%7}, {%8,%9}, {%0,%1,%2,%3};\n"
        : "+f"(d[0]), "+f"(d[1]), "+f"(d[2]), "+f"(d[3])
        : "r"(a[0]), "r"(a[1]), "r"(a[2]), "r"(a[3]), "r"(b[0]), "r"(b[1]));
}

// ---------------- 1) x NCHW -> NHWC ----------------
__global__ void k_transpose_x(const float* __restrict__ x) {
    __shared__ float tile[32][33];
    int b   = blockIdx.z;
    int hw0 = blockIdx.x * 32;
    int c0  = blockIdx.y * 32;
    int tx = threadIdx.x, ty = threadIdx.y;
    tile[ty][tx] = x[(b * CIN + c0 + ty) * HW + hw0 + tx];
    __syncthreads();
    g_xt[(b * HW + hw0 + ty) * CIN + c0 + tx] = tile[tx][ty];
}

// ---------------- 2) weight prep ----------------
// Main A image per (ch,tap): linear idx = ((s*8 + mt)*32 + lane)*4 + q
//   r = mt*16 + (q&1)*8 + g,  k = s*8 + t + (q>>1)*4   (g=lane>>2, t=lane&3)
// Offset A image per tap: idx = ((s*2 + mt)*32 + lane)*4 + q, rows >=18 zero.
__global__ void k_prep_w(const float* __restrict__ dw, const float* __restrict__ ow) {
    int tid = blockIdx.x * 256 + threadIdx.x;
    if (tid < 2 * 9 * 16384) {
        int img  = tid >> 14;                  // ch*9 + tap
        int idx  = tid & 16383;
        int q    = idx & 3;
        int lane = (idx >> 2) & 31;
        int mt   = (idx >> 7) & 7;
        int s    = idx >> 10;
        int g = lane >> 2, t = lane & 3;
        int ch = img / 9, tap = img - ch * 9;
        int r = mt * 16 + (q & 1) * 8 + g;
        int k = s * 8 + t + (q >> 1) * 4;
        g_wa[tid] = to_tf32(dw[((ch * 128 + r) * CIN + k) * 9 + tap]);
    } else if (tid < 2 * 9 * 16384 + 9 * 4096) {
        int j   = tid - 2 * 9 * 16384;
        int tap = j >> 12;
        int idx = j & 4095;
        int q    = idx & 3;
        int lane = (idx >> 2) & 31;
        int mt   = (idx >> 7) & 1;
        int s    = idx >> 8;
        int g = lane >> 2, t = lane & 3;
        int r = mt * 16 + (q & 1) * 8 + g;
        int k = s * 8 + t + (q >> 1) * 4;
        g_owa[j] = (r < 18) ? to_tf32(ow[(r * CIN + k) * 9 + tap]) : 0.0f;
    }
}

// ---------------- 3) offset conv via mma.sync ----------------
// grid 256: block = 128 consecutive px (2 rows). 8 warps x 16 px each,
// M=32 (rows 0..17 valid). Warp-independent: only __syncwarp().
__global__ void __launch_bounds__(256, 2) k_offset_mma(const float* __restrict__ ob) {
    extern __shared__ float p_sm[];             // [128][BSTR]
    int tid = threadIdx.x, wid = tid >> 5, lane = tid & 31;
    int g = lane >> 2, t = lane & 3;
    int base = blockIdx.x * 128;                // global px base
    int b    = base >> 12;
    int rem  = base & 4095;                     // row0*64
    int row0 = rem >> 6;
    int wn   = wid * 16;

    float acc[2][2][4];
#pragma unroll
    for (int mt = 0; mt < 2; ++mt)
#pragma unroll
        for (int nt = 0; nt < 2; ++nt)
#pragma unroll
            for (int j = 0; j < 4; ++j) acc[mt][nt][j] = 0.f;

    const float4* xb4 = reinterpret_cast<const float4*>(g_xt + b * HW * CIN);

    for (int tap = 0; tap < 9; ++tap) {
        int ty = tap / 3 - 1, tx = tap % 3 - 1;
        // stage B: warp's own 16 px, lane = channel quad (coalesced row copy)
#pragma unroll 4
        for (int it = 0; it < 16; ++it) {
            int p   = wn + it;
            int row = row0 + (p >> 6);
            int col = p & 63;
            int y = row + ty, xc = col + tx;
            float4 v = {0.f, 0.f, 0.f, 0.f};
            if ((unsigned)y < 64u && (unsigned)xc < 64u)
                v = xb4[((y << 6) + xc) * 32 + lane];
            v.x = to_tf32(v.x); v.y = to_tf32(v.y);
            v.z = to_tf32(v.z); v.w = to_tf32(v.w);
            *reinterpret_cast<float4*>(p_sm + p * BSTR + lane * 4) = v;
        }
        __syncwarp();

        const float4* aimg = reinterpret_cast<const float4*>(g_owa) + tap * 1024;
        const uint32_t* pB = reinterpret_cast<const uint32_t*>(p_sm)
                             + (wn + g) * BSTR + t;
#pragma unroll
        for (int s = 0; s < 16; ++s) {
            float4 fa0 = aimg[(s * 2) * 32 + lane];
            float4 fa1 = aimg[(s * 2 + 1) * 32 + lane];
            uint32_t A0[4] = {__float_as_uint(fa0.x), __float_as_uint(fa0.y),
                              __float_as_uint(fa0.z), __float_as_uint(fa0.w)};
            uint32_t A1[4] = {__float_as_uint(fa1.x), __float_as_uint(fa1.y),
                              __float_as_uint(fa1.z), __float_as_uint(fa1.w)};
            int k0 = s * 8;
#pragma unroll
            for (int nt = 0; nt < 2; ++nt) {
                uint32_t Bv[2];
                Bv[0] = pB[nt * 8 * BSTR + k0];
                Bv[1] = pB[nt * 8 * BSTR + k0 + 4];
                mma_16n8k8(acc[0][nt], A0, Bv);
                mma_16n8k8(acc[1][nt], A1, Bv);
            }
        }
        __syncwarp();   // before next tap overwrites warp's B region
    }

    // epilogue: rows r<18 only
#pragma unroll
    for (int mt = 0; mt < 2; ++mt)
#pragma unroll
        for (int h = 0; h < 2; ++h) {
            int r = mt * 16 + h * 8 + g;
            if (r < 18) {
                float bias = ob[r];
#pragma unroll
                for (int nt = 0; nt < 2; ++nt) {
                    int n = wn + nt * 8 + 2 * t;
                    float2 o = {acc[mt][nt][h * 2] + bias,
                                acc[mt][nt][h * 2 + 1] + bias};
                    *reinterpret_cast<float2*>(
                        g_off + (b * 18 + r) * HW + rem + n) = o;
                }
            }
        }
}

// ---------------- coord helper ----------------
__device__ __forceinline__ void compute_coords(int tap, int hob, int b,
                                               int4* ci, float4* cf, int p) {
    int row = hob + (p >> 6), col = p & 63;
    float dy = g_off[(b * 18 + tap * 2)     * HW + hob * 64 + p];
    float dx = g_off[(b * 18 + tap * 2 + 1) * HW + hob * 64 + p];
    float sy = (float)(row - 1 + tap / 3) + dy;
    float sx = (float)(col - 1 + tap % 3) + dx;
    float fy = floorf(sy), fx = floorf(sx);
    int y0 = (int)fy, x0 = (int)fx;
    float wy = sy - fy, wx = sx - fx;
    float yv0 = ((unsigned)y0       < 64u) ? 1.f : 0.f;
    float yv1 = ((unsigned)(y0 + 1) < 64u) ? 1.f : 0.f;
    float xv0 = ((unsigned)x0       < 64u) ? 1.f : 0.f;
    float xv1 = ((unsigned)(x0 + 1) < 64u) ? 1.f : 0.f;
    int yc0 = max(0, min(63, y0));
    int yc1 = max(0, min(63, y0 + 1));
    int xc0 = max(0, min(63, x0));
    int xc1 = max(0, min(63, x0 + 1));
    int4 o;
    o.x = (yc0 * 64 + xc0) * 32;    // float4 units (CIN/4)
    o.y = (yc0 * 64 + xc1) * 32;
    o.z = (yc1 * 64 + xc0) * 32;
    o.w = (yc1 * 64 + xc1) * 32;
    float4 w;
    w.x = (1.f - wy) * (1.f - wx) * yv0 * xv0;
    w.y = (1.f - wy) * wx         * yv0 * xv1;
    w.z = wy         * (1.f - wx) * yv1 * xv0;
    w.w = wy         * wx         * yv1 * xv1;
    ci[p] = o;
    cf[p] = w;
}

// ---------------- 4) mma.sync tf32 main ----------------
// blockIdx.x = (b*32 + ho2)*2 + ch. M=128 couts, N=128 px (2 rows).
// 8 warps: warp tile 32c x 64px. A fragments DIRECT LDG from g_wa.
__global__ void __launch_bounds__(256, 2) k_main(const float* __restrict__ dconv_b) {
    extern __shared__ float sm[];
    float* p_sm = sm + OFF_P;
    int4*   ci  = reinterpret_cast<int4*>(sm + OFF_CI);     // [2][128]
    float4* cf  = reinterpret_cast<float4*>(sm + OFF_CF);   // [2][128]

    int tid = threadIdx.x, wid = tid >> 5, lane = tid & 31;
    int bi  = blockIdx.x;
    int ch  = bi & 1;
    int ho2 = (bi >> 1) & 31;
    int b   = bi >> 6;
    int hob = ho2 * 2;

    int g = lane >> 2, t = lane & 3;
    int wm  = (wid >> 1) * 32;                 // cout base (0/32/64/96)
    int wn  = (wid & 1) * 64;                  // px base (0/64)
    int mt0 = wm >> 4;

    float acc[2][8][4];
#pragma unroll
    for (int im = 0; im < 2; ++im)
#pragma unroll
        for (int in = 0; in < 8; ++in)
#pragma unroll
            for (int j = 0; j < 4; ++j) acc[im][in][j] = 0.f;

    const float4* xb4 = reinterpret_cast<const float4*>(g_xt + b * HW * CIN);
    const uint32_t* pB = reinterpret_cast<const uint32_t*>(p_sm) + (wn + g) * BSTR + t;

    if (tid < 128) compute_coords(0, hob, b, ci, cf, tid);
    __syncthreads();

    for (int tap = 0; tap < 9; ++tap) {
        int buf = tap & 1;

        // ---- gather B: 128 px, warp = px, lane = channel quad ----
        const int4*   cib = ci + buf * 128;
        const float4* cfb = cf + buf * 128;
#pragma unroll 1
        for (int px = wid; px < 128; px += 8) {
            int4   o = cib[px];
            float4 w = cfb[px];
            float4 v00 = xb4[o.x + lane];
            float4 v01 = xb4[o.y + lane];
            float4 v10 = xb4[o.z + lane];
            float4 v11 = xb4[o.w + lane];
            float4 val;
            val.x = to_tf32(fmaf(w.w, v11.x, fmaf(w.z, v10.x,
                            fmaf(w.y, v01.x, w.x * v00.x))));
            val.y = to_tf32(fmaf(w.w, v11.y, fmaf(w.z, v10.y,
                            fmaf(w.y, v01.y, w.x * v00.y))));
            val.z = to_tf32(fmaf(w.w, v11.z, fmaf(w.z, v10.z,
                            fmaf(w.y, v01.z, w.x * v00.z))));
            val.w = to_tf32(fmaf(w.w, v11.w, fmaf(w.z, v10.w,
                            fmaf(w.y, v01.w, w.x * v00.w))));
            *reinterpret_cast<float4*>(p_sm + px * BSTR + lane * 4) = val;
        }

        // ---- coords for next tap (overlapped) ----
        if (tap < 8 && tid < 128)
            compute_coords(tap + 1, hob, b, ci + ((tap + 1) & 1) * 128,
                           cf + ((tap + 1) & 1) * 128, tid);
        __syncthreads();

        // ---- MMA: A fragments direct LDG, 1-step prefetch ----
        const float4* wAt = reinterpret_cast<const float4*>(
            g_wa + (ch * 9 + tap) * 16384) + mt0 * 32 + lane;
        float4 fa0 = wAt[0];
        float4 fa1 = wAt[32];
#pragma unroll
        for (int s = 0; s < 16; ++s) {
            float4 na0, na1;
            if (s < 15) {
                na0 = wAt[(s + 1) * 256];
                na1 = wAt[(s + 1) * 256 + 32];
            }
            uint32_t A0[4] = {__float_as_uint(fa0.x), __float_as_uint(fa0.y),
                              __float_as_uint(fa0.z), __float_as_uint(fa0.w)};
            uint32_t A1[4] = {__float_as_uint(fa1.x), __float_as_uint(fa1.y),
                              __float_as_uint(fa1.z), __float_as_uint(fa1.w)};
            int k0 = s * 8;
#pragma unroll
            for (int in = 0; in < 8; ++in) {
                uint32_t Bv[2];
                Bv[0] = pB[in * 8 * BSTR + k0];
                Bv[1] = pB[in * 8 * BSTR + k0 + 4];
                mma_16n8k8(acc[0][in], A0, Bv);
                mma_16n8k8(acc[1][in], A1, Bv);
            }
            if (s < 15) { fa0 = na0; fa1 = na1; }
        }
        __syncthreads();   // before next tap overwrites p_sm
    }

    // ---- epilogue ----
#pragma unroll
    for (int im = 0; im < 2; ++im) {
        int r0 = ch * 128 + wm + im * 16 + g;
        int r1 = r0 + 8;
        float b0 = dconv_b[r0];
        float b1 = dconv_b[r1];
#pragma unroll
        for (int in = 0; in < 8; ++in) {
            int n   = wn + in * 8 + 2 * t;
            int row = hob + (n >> 6);
            int col = n & 63;
            float2 o0 = {acc[im][in][0] + b0, acc[im][in][1] + b0};
            float2 o1 = {acc[im][in][2] + b1, acc[im][in][3] + b1};
            *reinterpret_cast<float2*>(
                g_y + (b * COUT + r0) * HW + row * 64 + col) = o0;
            *reinterpret_cast<float2*>(
                g_y + (b * COUT + r1) * HW + row * 64 + col) = o1;
        }
    }
}

// ---------------- 5a) BN statistics (deterministic) ----------------
__global__ void k_bn_reduce() {
    int c = blockIdx.x;
    int tid = threadIdx.x;
    float s = 0.f, s2 = 0.f;
    for (int b = 0; b < Bn; ++b) {
        const float4* p = reinterpret_cast<const float4*>(g_y + (b * COUT + c) * HW);
        for (int i = tid; i < HW / 4; i += 256) {
            float4 v = p[i];
            s  += v.x + v.y + v.z + v.w;
            s2 += v.x * v.x + v.y * v.y + v.z * v.z + v.w * v.w;
        }
    }
    __shared__ float rs[256], rs2[256];
    rs[tid] = s; rs2[tid] = s2;
    __syncthreads();
    for (int o = 128; o > 0; o >>= 1) {
        if (tid < o) { rs[tid] += rs[tid + o]; rs2[tid] += rs2[tid + o]; }
        __syncthreads();
    }
    if (tid == 0) {
        float inv = 1.0f / (Bn * HW);
        float m = rs[0] * inv;
        float var = rs2[0] * inv - m * m;
        g_mean[c] = m;
        g_rstd[c] = rsqrtf(var + 1e-5f);
    }
}

// ---------------- 5b) normalize + SiLU ----------------
__global__ void k_finalize(const float* __restrict__ gamma,
                           const float* __restrict__ beta,
                           float* __restrict__ out) {
    int idx = blockIdx.x * 256 + threadIdx.x;
    int c = (idx >> 10) & 255;
    float m = g_mean[c];
    float scale = g_rstd[c] * gamma[c];
    float shift = beta[c] - m * scale;
    float4 v = reinterpret_cast<const float4*>(g_y)[idx];
    float4 o;
    { float z = v.x * scale + shift; o.x = z / (1.f + __expf(-z)); }
    { float z = v.y * scale + shift; o.y = z / (1.f + __expf(-z)); }
    { float z = v.z * scale + shift; o.z = z / (1.f + __expf(-z)); }
    { float z = v.w * scale + shift; o.w = z / (1.f + __expf(-z)); }
    reinterpret_cast<float4*>(out)[idx] = o;
}

// ---------------------------------------------------------------------------
extern "C" void kernel_launch(void* const* d_in, const int* in_sizes, int n_in,
                              void* d_out, int out_size) {
    const float* x  = (const float*)d_in[0];
    const float* ow = (const float*)d_in[1];
    const float* ob = (const float*)d_in[2];
    const float* dw = (const float*)d_in[3];
    const float* db = (const float*)d_in[4];
    const float* ga = (const float*)d_in[5];
    const float* be = (const float*)d_in[6];
    float* out = (float*)d_out;

    cudaFuncSetAttribute(k_offset_mma,
                         cudaFuncAttributeMaxDynamicSharedMemorySize, OSM_BYTES);
    cudaFuncSetAttribute(k_main,
                         cudaFuncAttributeMaxDynamicSharedMemorySize, SMEM_BYTES);

    k_transpose_x<<<dim3(HW / 32, CIN / 32, Bn), dim3(32, 32)>>>(x);
    k_prep_w<<<(2 * 9 * 16384 + 9 * 4096 + 255) / 256, 256>>>(dw, ow);
    k_offset_mma<<<256, 256, OSM_BYTES>>>(ob);
    k_main<<<512, 256, SMEM_BYTES>>>(db);
    k_bn_reduce<<<COUT, 256>>>();
    k_finalize<<<8192, 256>>>(ga, be, out);
}